// round 2
// baseline (speedup 1.0000x reference)
#include <cuda_runtime.h>
#include <math.h>
#include <stdint.h>
#include <stddef.h>

// ---------------- problem constants ----------------
#define SEQN   1024
#define DIMN   2048
#define NTOK   2048          // BSZ*SEQ
#define NH     16
#define HD     128
#define AL     10
#define PLD    1056          // prob row stride: 1024 seq + 10 adapter + 22 pad
#define SCALE_Q 0.08838834764831845f   // 1/sqrt(128)

#define GP     36            // smem pitch (floats)
#define STG128 (128*GP)
#define STG64  (64*GP)

// ---------------- device scratch (no allocation allowed) ----------------
__device__ float g_q [NTOK*DIMN];
__device__ float g_k [NTOK*DIMN];
__device__ float g_v [NTOK*DIMN];
__device__ float g_ao[NTOK*DIMN];
__device__ float g_ak[AL*DIMN];
__device__ float g_av[AL*DIMN];
__device__ float g_s [(size_t)32*SEQN*PLD];   // per (b,h): 1024 x 1056 probs/scores

// ---------------- helpers ----------------
__device__ __forceinline__ uint32_t ld_tf32(const float* p) {
    uint32_t u;
    asm("cvt.rna.tf32.f32 %0, %1;" : "=r"(u) : "f"(*p));
    return u;
}

__device__ __forceinline__ void mma_tf32(float c[4], const uint32_t a[4], const uint32_t b[2]) {
    asm volatile(
        "mma.sync.aligned.m16n8k8.row.col.f32.tf32.tf32.f32 "
        "{%0,%1,%2,%3}, {%4,%5,%6,%7}, {%8,%9}, {%0,%1,%2,%3};"
        : "+f"(c[0]), "+f"(c[1]), "+f"(c[2]), "+f"(c[3])
        : "r"(a[0]), "r"(a[1]), "r"(a[2]), "r"(a[3]), "r"(b[0]), "r"(b[1]));
}

__device__ __forceinline__ void cpa16(float* s, const float* g) {
    unsigned sa = (unsigned)__cvta_generic_to_shared(s);
    asm volatile("cp.async.cg.shared.global [%0], [%1], 16;\n" :: "r"(sa), "l"(g));
}
__device__ __forceinline__ void cpa_commit() { asm volatile("cp.async.commit_group;\n" ::); }
#define CP_WAIT1() asm volatile("cp.async.wait_group 1;\n" ::)
#define CP_WAIT0() asm volatile("cp.async.wait_group 0;\n" ::)

// fragment loop over one 32-k stage. MT = #m16 tiles per warp in M.
// Ab points at warp's A rows [MT*16][32] pitch GP; Bb at warp's B cols [32 n][32 k].
template<int MT>
__device__ __forceinline__ void mma_stage(const float* Ab, const float* Bb,
                                          float (*acc)[4][4], int ar, int ac) {
#pragma unroll
    for (int ks = 0; ks < 4; ks++) {
        const int k0 = ks * 8;
        uint32_t af[MT][4], bf[4][2];
#pragma unroll
        for (int mt = 0; mt < MT; mt++) {
            const float* p = Ab + (mt*16 + ar)*GP + k0 + ac;
            af[mt][0] = ld_tf32(p);
            af[mt][1] = ld_tf32(p + 8*GP);
            af[mt][2] = ld_tf32(p + 4);
            af[mt][3] = ld_tf32(p + 8*GP + 4);
        }
#pragma unroll
        for (int nt = 0; nt < 4; nt++) {
            const float* p = Bb + (nt*8 + ar)*GP + k0 + ac;
            bf[nt][0] = ld_tf32(p);
            bf[nt][1] = ld_tf32(p + 4);
        }
#pragma unroll
        for (int mt = 0; mt < MT; mt++)
#pragma unroll
            for (int nt = 0; nt < 4; nt++) mma_tf32(acc[mt][nt], af[mt], bf[nt]);
    }
}

// 128x128 C block: C[m][n] = sum_k A[m][k]*B[n][k]. A,B pre-offset to block origin.
__device__ __forceinline__ void gemm128(const float* __restrict__ A, int lda,
                                        const float* __restrict__ B, int ldb,
                                        int nk, float (*acc)[4][4]) {
    extern __shared__ float smdyn[];
    float* As = smdyn;
    float* Bs = smdyn + 2*STG128;
    const int t = threadIdx.x, lane = t & 31, wid = t >> 5;
    const int wm = wid >> 2, wn = wid & 3, ar = lane >> 2, ac = lane & 3;
    const int lr = t >> 3, lc = (t & 7) * 4;

    auto issue = [&](int kt, int buf) {
        float* Asb = As + buf*STG128;
        float* Bsb = Bs + buf*STG128;
        const float* Ag = A + kt*32;
        const float* Bg = B + kt*32;
#pragma unroll
        for (int i = 0; i < 4; i++) {
            int r = lr + i*32;
            cpa16(Asb + r*GP + lc, Ag + (size_t)r*lda + lc);
            cpa16(Bsb + r*GP + lc, Bg + (size_t)r*ldb + lc);
        }
        cpa_commit();
    };

    issue(0, 0);
    for (int kt = 0; kt < nk; kt++) {
        if (kt + 1 < nk) { issue(kt + 1, (kt + 1) & 1); CP_WAIT1(); }
        else             { CP_WAIT0(); }
        __syncthreads();
        mma_stage<4>(As + (kt&1)*STG128 + (wm*64)*GP,
                     Bs + (kt&1)*STG128 + (wn*32)*GP, acc, ar, ac);
        __syncthreads();
    }
}

// ---------------- kernel 1: adapter projections a_k, a_v ----------------
__global__ __launch_bounds__(256) void akv_kernel(const float* __restrict__ adapter,
                                                  const float* __restrict__ wk,
                                                  const float* __restrict__ wv) {
    extern __shared__ float sad[];   // 10*2048 floats = 80KB
    const int t = threadIdx.x, lane = t & 31, wid = t >> 5;
    for (int i = t; i < (AL*DIMN)/4; i += 256)
        ((float4*)sad)[i] = ((const float4*)adapter)[i];
    __syncthreads();

    int gw = blockIdx.x * 8 + wid;          // 0..4095
    const float* W = (gw < DIMN) ? wk : wv;
    float* O       = (gw < DIMN) ? g_ak : g_av;
    int n = gw & (DIMN - 1);
    const float* Wr = W + (size_t)n * DIMN;

    float acc[AL];
#pragma unroll
    for (int j = 0; j < AL; j++) acc[j] = 0.f;

    for (int it = 0; it < DIMN/32; it++) {
        int k = it*32 + lane;
        float w = Wr[k];
#pragma unroll
        for (int j = 0; j < AL; j++) acc[j] += sad[j*DIMN + k] * w;
    }
#pragma unroll
    for (int j = 0; j < AL; j++) {
        float v = acc[j];
#pragma unroll
        for (int o = 16; o; o >>= 1) v += __shfl_xor_sync(0xffffffffu, v, o);
        if (lane == 0) O[(size_t)j*DIMN + n] = v;
    }
}

// ---------------- kernel 2: fused QKV projection + RoPE ----------------
__global__ __launch_bounds__(256) void qkv_kernel(const float* __restrict__ x,
                                                  const float* __restrict__ wq,
                                                  const float* __restrict__ wk,
                                                  const float* __restrict__ wv,
                                                  const float* __restrict__ fc,
                                                  const float* __restrict__ fs) {
    const int z = blockIdx.z;
    const float* B = (z == 0) ? wq : (z == 1) ? wk : wv;
    float* C       = (z == 0) ? g_q : (z == 1) ? g_k : g_v;
    const int bm = blockIdx.y * 128, bn = blockIdx.x * 128;

    float acc[4][4][4];
#pragma unroll
    for (int i = 0; i < 4; i++)
#pragma unroll
        for (int j = 0; j < 4; j++)
#pragma unroll
            for (int e = 0; e < 4; e++) acc[i][j][e] = 0.f;

    gemm128(x + (size_t)bm*DIMN, DIMN, B + (size_t)bn*DIMN, DIMN, DIMN/32, acc);

    const int lane = threadIdx.x & 31, wid = threadIdx.x >> 5;
    const int wm = wid >> 2, wn = wid & 3, ar = lane >> 2, ac = lane & 3;
#pragma unroll
    for (int mt = 0; mt < 4; mt++)
#pragma unroll
        for (int nt = 0; nt < 4; nt++) {
            int r0 = bm + wm*64 + mt*16 + ar, r1 = r0 + 8;
            int col = bn + wn*32 + nt*8 + 2*ac;
            float a0 = acc[mt][nt][0], a1 = acc[mt][nt][1];
            float a2 = acc[mt][nt][2], a3 = acc[mt][nt][3];
            if (z < 2) {  // rope for q,k
                int p  = (col & (HD-1)) >> 1;
                int t0 = r0 & (SEQN-1), t1 = r1 & (SEQN-1);
                float c0 = fc[t0*(HD/2) + p], s0 = fs[t0*(HD/2) + p];
                float c1 = fc[t1*(HD/2) + p], s1 = fs[t1*(HD/2) + p];
                float b0 = a0*c0 - a1*s0, b1 = a0*s0 + a1*c0;
                float b2 = a2*c1 - a3*s1, b3 = a2*s1 + a3*c1;
                if (z == 0) { b0 *= SCALE_Q; b1 *= SCALE_Q; b2 *= SCALE_Q; b3 *= SCALE_Q; }
                a0 = b0; a1 = b1; a2 = b2; a3 = b3;
            }
            *(float2*)(C + (size_t)r0*DIMN + col) = make_float2(a0, a1);
            *(float2*)(C + (size_t)r1*DIMN + col) = make_float2(a2, a3);
        }
}

// ---------------- kernel 3: S = Q K^T (batched, lower-triangular blocks only) ----
__global__ __launch_bounds__(256) void s_kernel() {
    if (blockIdx.x > blockIdx.y) return;  // fully masked tile (softmax reads j<=i only)
    const int z = blockIdx.z, b = z >> 4, h = z & (NH-1);
    const int bm = blockIdx.y * 128, bn = blockIdx.x * 128;
    const float* Q = g_q + (size_t)b*SEQN*DIMN + h*HD;
    const float* K = g_k + (size_t)b*SEQN*DIMN + h*HD;

    float acc[4][4][4];
#pragma unroll
    for (int i = 0; i < 4; i++)
#pragma unroll
        for (int j = 0; j < 4; j++)
#pragma unroll
            for (int e = 0; e < 4; e++) acc[i][j][e] = 0.f;

    gemm128(Q + (size_t)bm*DIMN, DIMN, K + (size_t)bn*DIMN, DIMN, HD/32, acc);

    float* S = g_s + (size_t)z*SEQN*PLD;
    const int lane = threadIdx.x & 31, wid = threadIdx.x >> 5;
    const int wm = wid >> 2, wn = wid & 3, ar = lane >> 2, ac = lane & 3;
#pragma unroll
    for (int mt = 0; mt < 4; mt++)
#pragma unroll
        for (int nt = 0; nt < 4; nt++) {
            int r0 = bm + wm*64 + mt*16 + ar, r1 = r0 + 8;
            int col = bn + wn*32 + nt*8 + 2*ac;
            *(float2*)(S + (size_t)r0*PLD + col) = make_float2(acc[mt][nt][0], acc[mt][nt][1]);
            *(float2*)(S + (size_t)r1*PLD + col) = make_float2(acc[mt][nt][2], acc[mt][nt][3]);
        }
}

// ---------------- kernel 4: row softmax (causal + gate2) + adapter branch ----------
__global__ __launch_bounds__(256) void sm_kernel(const float* __restrict__ g1,
                                                 const float* __restrict__ g2v,
                                                 const int* __restrict__ vsp) {
    __shared__ float srow[SEQN];
    __shared__ float sq[HD];
    __shared__ float red[40];
    __shared__ float sad[AL];
    const int i = blockIdx.x, z = blockIdx.y, b = z >> 4, h = z & (NH-1);
    const int t = threadIdx.x, lane = t & 31, wid = t >> 5;
    const int vs = vsp[0];
    const int n = i + 1;
    float* Prow = g_s + (size_t)z*SEQN*PLD + (size_t)i*PLD;
    const float g2 = g2v[h];

    for (int j = t; j < n; j += 256) {
        float v = Prow[j];
        if (i >= vs + AL && j >= vs && j < vs + AL) v += g2;
        srow[j] = v;
    }
    if (t < HD) sq[t] = g_q[((size_t)(b*SEQN + i))*DIMN + h*HD + t];
    __syncthreads();

    // row max
    float lm = -3.0e38f;
    for (int j = t; j < n; j += 256) lm = fmaxf(lm, srow[j]);
#pragma unroll
    for (int o = 16; o; o >>= 1) lm = fmaxf(lm, __shfl_xor_sync(0xffffffffu, lm, o));
    if (lane == 0) red[wid] = lm;
    __syncthreads();
    if (t == 0) {
        float m = red[0];
        for (int w = 1; w < 8; w++) m = fmaxf(m, red[w]);
        red[16] = m;
    }
    __syncthreads();
    const float mx = red[16];

    // exp + sum
    float ls = 0.f;
    for (int j = t; j < n; j += 256) {
        float e = expf(srow[j] - mx);
        srow[j] = e;
        ls += e;
    }
#pragma unroll
    for (int o = 16; o; o >>= 1) ls += __shfl_xor_sync(0xffffffffu, ls, o);
    if (lane == 0) red[24 + wid] = ls;
    __syncthreads();
    if (t == 0) {
        float s = 0.f;
        for (int w = 0; w < 8; w++) s += red[24 + w];
        red[17] = 1.0f / s;
    }
    __syncthreads();
    const float inv = red[17];

    for (int j = t; j < n; j += 256)     Prow[j] = srow[j] * inv;
    for (int j = n + t; j < SEQN; j += 256) Prow[j] = 0.f;
    if (t < PLD - SEQN - AL) Prow[SEQN + AL + t] = 0.f;

    // adapter scores (q already scaled by 1/sqrt(hd))
    if (t < AL) {
        float d = 0.f;
        const float* ak = g_ak + (size_t)t*DIMN + h*HD;
#pragma unroll 8
        for (int e = 0; e < HD; e++) d += sq[e] * ak[e];
        sad[t] = d;
    }
    __syncthreads();
    if (t == 0) {
        float m = sad[0];
        for (int j = 1; j < AL; j++) m = fmaxf(m, sad[j]);
        float s = 0.f, e[AL];
        for (int j = 0; j < AL; j++) { e[j] = expf(sad[j] - m); s += e[j]; }
        float f = tanhf(g1[h]) / s;
        for (int j = 0; j < AL; j++) Prow[SEQN + j] = e[j] * f;
    }
}

// ---------------- kernel 5: out = P @ [V ; a_v]  (K = 1056) ----------------
__global__ __launch_bounds__(256) void pv_kernel() {
    extern __shared__ float smdyn[];
    float* As = smdyn;               // 2 x 64 x GP
    float* Bs = smdyn + 2*STG64;     // 2 x 128 x GP
    const int t = threadIdx.x, lane = t & 31, wid = t >> 5;
    const int wm = wid >> 2, wn = wid & 3, ar = lane >> 2, ac = lane & 3;
    const int bm = blockIdx.y, z = blockIdx.z, b = z >> 4, h = z & (NH-1);
    const float* P  = g_s + (size_t)z*SEQN*PLD + (size_t)bm*64*PLD;
    const float* Vb = g_v + (size_t)b*SEQN*DIMN + h*HD;
    const float* Av = g_av + h*HD;
    const int lr = t >> 3, lc = (t & 7) * 4;

    float acc[2][4][4];
#pragma unroll
    for (int i = 0; i < 2; i++)
#pragma unroll
        for (int j = 0; j < 4; j++)
#pragma unroll
            for (int e = 0; e < 4; e++) acc[i][j][e] = 0.f;

    float4 vr[4];

    auto ldV = [&](int kt) {
        int j = kt*32 + lane;
        const float* src;
        if (j < SEQN) src = Vb + (size_t)j*DIMN + wid*16;
        else { int jj = j - SEQN; if (jj > AL-1) jj = AL-1; src = Av + (size_t)jj*DIMN + wid*16; }
#pragma unroll
        for (int q = 0; q < 4; q++) vr[q] = *(const float4*)(src + q*4);
    };
    auto stV = [&](int buf) {   // transpose: Bs[d][j_local], bank-conflict-free (bank = lane)
        float* Bsb = Bs + buf*STG128;
#pragma unroll
        for (int q = 0; q < 4; q++) {
            int d = wid*16 + q*4;
            Bsb[(d+0)*GP + lane] = vr[q].x;
            Bsb[(d+1)*GP + lane] = vr[q].y;
            Bsb[(d+2)*GP + lane] = vr[q].z;
            Bsb[(d+3)*GP + lane] = vr[q].w;
        }
    };
    auto issueA = [&](int kt, int buf) {
        float* Asb = As + buf*STG64;
        const float* Ag = P + kt*32;
#pragma unroll
        for (int ii = 0; ii < 2; ii++) {
            int r = lr + ii*32;
            cpa16(Asb + r*GP + lc, Ag + (size_t)r*PLD + lc);
        }
        cpa_commit();
    };

    ldV(0);
    issueA(0, 0);
    const int NK = PLD / 32;   // 33
    for (int kt = 0; kt < NK; kt++) {
        int buf = kt & 1;
        stV(buf);
        if (kt + 1 < NK) { issueA(kt + 1, buf ^ 1); CP_WAIT1(); }
        else             { CP_WAIT0(); }
        __syncthreads();
        if (kt + 1 < NK) ldV(kt + 1);   // prefetch next V tile into regs, overlaps mma
        mma_stage<2>(As + buf*STG64 + (wm*32)*GP,
                     Bs + buf*STG128 + (wn*32)*GP, acc, ar, ac);
        __syncthreads();
    }

#pragma unroll
    for (int mt = 0; mt < 2; mt++)
#pragma unroll
        for (int nt = 0; nt < 4; nt++) {
            int i0 = bm*64 + wm*32 + mt*16 + ar, i1 = i0 + 8;
            int d = wn*32 + nt*8 + 2*ac;
            float* o0 = g_ao + ((size_t)(b*SEQN + i0))*DIMN + h*HD + d;
            float* o1 = g_ao + ((size_t)(b*SEQN + i1))*DIMN + h*HD + d;
            *(float2*)o0 = make_float2(acc[mt][nt][0], acc[mt][nt][1]);
            *(float2*)o1 = make_float2(acc[mt][nt][2], acc[mt][nt][3]);
        }
}

// ---------------- kernel 6: final projection out = ao @ wo^T ----------------
__global__ __launch_bounds__(256) void wo_kernel(const float* __restrict__ wo,
                                                 float* __restrict__ out) {
    const int bm = blockIdx.y * 128, bn = blockIdx.x * 128;
    float acc[4][4][4];
#pragma unroll
    for (int i = 0; i < 4; i++)
#pragma unroll
        for (int j = 0; j < 4; j++)
#pragma unroll
            for (int e = 0; e < 4; e++) acc[i][j][e] = 0.f;

    gemm128(g_ao + (size_t)bm*DIMN, DIMN, wo + (size_t)bn*DIMN, DIMN, DIMN/32, acc);

    const int lane = threadIdx.x & 31, wid = threadIdx.x >> 5;
    const int wm = wid >> 2, wn = wid & 3, ar = lane >> 2, ac = lane & 3;
#pragma unroll
    for (int mt = 0; mt < 4; mt++)
#pragma unroll
        for (int nt = 0; nt < 4; nt++) {
            int r0 = bm + wm*64 + mt*16 + ar, r1 = r0 + 8;
            int col = bn + wn*32 + nt*8 + 2*ac;
            *(float2*)(out + (size_t)r0*DIMN + col) = make_float2(acc[mt][nt][0], acc[mt][nt][1]);
            *(float2*)(out + (size_t)r1*DIMN + col) = make_float2(acc[mt][nt][2], acc[mt][nt][3]);
        }
}

// ---------------- launch ----------------
extern "C" void kernel_launch(void* const* d_in, const int* in_sizes, int n_in,
                              void* d_out, int out_size) {
    const float* x       = (const float*)d_in[0];
    const float* adapter = (const float*)d_in[1];
    // d_in[2] = mask (structure known: triu -1e9, handled analytically)
    const float* fc      = (const float*)d_in[3];
    const float* fs      = (const float*)d_in[4];
    const float* wq      = (const float*)d_in[5];
    const float* wk      = (const float*)d_in[6];
    const float* wv      = (const float*)d_in[7];
    const float* wo      = (const float*)d_in[8];
    const float* g1      = (const float*)d_in[9];
    const float* g2      = (const float*)d_in[10];
    const int*   vs      = (const int*)  d_in[11];
    float* out = (float*)d_out;

    const int smGemm = 2 * 2 * STG128 * (int)sizeof(float);          // 73728
    const int smPV   = (2*STG64 + 2*STG128) * (int)sizeof(float);    // 55296
    const int smAkv  = AL * DIMN * (int)sizeof(float);               // 81920
    cudaFuncSetAttribute(qkv_kernel, cudaFuncAttributeMaxDynamicSharedMemorySize, smGemm);
    cudaFuncSetAttribute(s_kernel,   cudaFuncAttributeMaxDynamicSharedMemorySize, smGemm);
    cudaFuncSetAttribute(wo_kernel,  cudaFuncAttributeMaxDynamicSharedMemorySize, smGemm);
    cudaFuncSetAttribute(pv_kernel,  cudaFuncAttributeMaxDynamicSharedMemorySize, smPV);
    cudaFuncSetAttribute(akv_kernel, cudaFuncAttributeMaxDynamicSharedMemorySize, smAkv);

    akv_kernel<<<512, 256, smAkv>>>(adapter, wk, wv);
    qkv_kernel<<<dim3(16, 16, 3), 256, smGemm>>>(x, wq, wk, wv, fc, fs);
    s_kernel<<<dim3(8, 8, 32), 256, smGemm>>>();
    sm_kernel<<<dim3(1024, 32), 256>>>(g1, g2, vs);
    pv_kernel<<<dim3(1, 16, 32), 256, smPV>>>();
    wo_kernel<<<dim3(16, 16), 256, smGemm>>>(wo, out);
}

// round 3
// speedup vs baseline: 1.4354x; 1.4354x over previous
#include <cuda_runtime.h>
#include <math.h>
#include <stdint.h>
#include <stddef.h>

// ---------------- problem constants ----------------
#define SEQN   1024
#define DIMN   2048
#define NTOK   2048          // BSZ*SEQ
#define NH     16
#define HD     128
#define AL     10
#define SCALE_Q 0.08838834764831845f   // 1/sqrt(128)

#define GP     36            // gemm smem pitch (floats)
#define STG128 (128*GP)

// flash tiling
#define BM 128
#define BN 64
#define KP 132               // K/V-staging smem pitch
#define VP 68                // V^T pitch
#define PP 68                // P pitch
#define KSTG (64*KP)         // 8448 floats per K/V stage

// ---------------- device scratch (no allocation allowed) ----------------
__device__ float g_q [NTOK*DIMN];
__device__ float g_k [NTOK*DIMN];
__device__ float g_v [NTOK*DIMN];
__device__ float g_ao[NTOK*DIMN];
__device__ float g_ak[AL*DIMN];
__device__ float g_av[AL*DIMN];

// ---------------- helpers ----------------
__device__ __forceinline__ uint32_t ld_tf32(const float* p) {
    uint32_t u;
    asm("cvt.rna.tf32.f32 %0, %1;" : "=r"(u) : "f"(*p));
    return u;
}

__device__ __forceinline__ void mma_tf32(float c[4], const uint32_t a[4], const uint32_t b[2]) {
    asm volatile(
        "mma.sync.aligned.m16n8k8.row.col.f32.tf32.tf32.f32 "
        "{%0,%1,%2,%3}, {%4,%5,%6,%7}, {%8,%9}, {%0,%1,%2,%3};"
        : "+f"(c[0]), "+f"(c[1]), "+f"(c[2]), "+f"(c[3])
        : "r"(a[0]), "r"(a[1]), "r"(a[2]), "r"(a[3]), "r"(b[0]), "r"(b[1]));
}

__device__ __forceinline__ void cpa16(float* s, const float* g) {
    unsigned sa = (unsigned)__cvta_generic_to_shared(s);
    asm volatile("cp.async.cg.shared.global [%0], [%1], 16;\n" :: "r"(sa), "l"(g));
}
__device__ __forceinline__ void cpa_commit() { asm volatile("cp.async.commit_group;\n" ::); }
#define CP_WAIT1() asm volatile("cp.async.wait_group 1;\n" ::)
#define CP_WAIT0() asm volatile("cp.async.wait_group 0;\n" ::)

__device__ __forceinline__ float qredmax(float v) {
    v = fmaxf(v, __shfl_xor_sync(0xffffffffu, v, 1));
    v = fmaxf(v, __shfl_xor_sync(0xffffffffu, v, 2));
    return v;
}
__device__ __forceinline__ float qredsum(float v) {
    v += __shfl_xor_sync(0xffffffffu, v, 1);
    v += __shfl_xor_sync(0xffffffffu, v, 2);
    return v;
}

// fragment loop over one 32-k stage (for the dense GEMMs)
template<int MT>
__device__ __forceinline__ void mma_stage(const float* Ab, const float* Bb,
                                          float (*acc)[4][4], int ar, int ac) {
#pragma unroll
    for (int ks = 0; ks < 4; ks++) {
        const int k0 = ks * 8;
        uint32_t af[MT][4], bf[4][2];
#pragma unroll
        for (int mt = 0; mt < MT; mt++) {
            const float* p = Ab + (mt*16 + ar)*GP + k0 + ac;
            af[mt][0] = ld_tf32(p);
            af[mt][1] = ld_tf32(p + 8*GP);
            af[mt][2] = ld_tf32(p + 4);
            af[mt][3] = ld_tf32(p + 8*GP + 4);
        }
#pragma unroll
        for (int nt = 0; nt < 4; nt++) {
            const float* p = Bb + (nt*8 + ar)*GP + k0 + ac;
            bf[nt][0] = ld_tf32(p);
            bf[nt][1] = ld_tf32(p + 4);
        }
#pragma unroll
        for (int mt = 0; mt < MT; mt++)
#pragma unroll
            for (int nt = 0; nt < 4; nt++) mma_tf32(acc[mt][nt], af[mt], bf[nt]);
    }
}

// 128x128 C block: C[m][n] = sum_k A[m][k]*B[n][k]. A,B pre-offset to block origin.
__device__ __forceinline__ void gemm128(const float* __restrict__ A, int lda,
                                        const float* __restrict__ B, int ldb,
                                        int nk, float (*acc)[4][4]) {
    extern __shared__ float smdyn[];
    float* As = smdyn;
    float* Bs = smdyn + 2*STG128;
    const int t = threadIdx.x, lane = t & 31, wid = t >> 5;
    const int wm = wid >> 2, wn = wid & 3, ar = lane >> 2, ac = lane & 3;
    const int lr = t >> 3, lc = (t & 7) * 4;

    auto issue = [&](int kt, int buf) {
        float* Asb = As + buf*STG128;
        float* Bsb = Bs + buf*STG128;
        const float* Ag = A + kt*32;
        const float* Bg = B + kt*32;
#pragma unroll
        for (int i = 0; i < 4; i++) {
            int r = lr + i*32;
            cpa16(Asb + r*GP + lc, Ag + (size_t)r*lda + lc);
            cpa16(Bsb + r*GP + lc, Bg + (size_t)r*ldb + lc);
        }
        cpa_commit();
    };

    issue(0, 0);
    for (int kt = 0; kt < nk; kt++) {
        if (kt + 1 < nk) { issue(kt + 1, (kt + 1) & 1); CP_WAIT1(); }
        else             { CP_WAIT0(); }
        __syncthreads();
        mma_stage<4>(As + (kt&1)*STG128 + (wm*64)*GP,
                     Bs + (kt&1)*STG128 + (wn*32)*GP, acc, ar, ac);
        __syncthreads();
    }
}

// ---------------- kernel 1: adapter projections a_k, a_v ----------------
__global__ __launch_bounds__(256) void akv_kernel(const float* __restrict__ adapter,
                                                  const float* __restrict__ wk,
                                                  const float* __restrict__ wv) {
    extern __shared__ float sad[];   // 10*2048 floats = 80KB
    const int t = threadIdx.x, lane = t & 31, wid = t >> 5;
    for (int i = t; i < (AL*DIMN)/4; i += 256)
        ((float4*)sad)[i] = ((const float4*)adapter)[i];
    __syncthreads();

    int gw = blockIdx.x * 8 + wid;          // 0..4095
    const float* W = (gw < DIMN) ? wk : wv;
    float* O       = (gw < DIMN) ? g_ak : g_av;
    int n = gw & (DIMN - 1);
    const float* Wr = W + (size_t)n * DIMN;

    float acc[AL];
#pragma unroll
    for (int j = 0; j < AL; j++) acc[j] = 0.f;

    for (int it = 0; it < DIMN/32; it++) {
        int k = it*32 + lane;
        float w = Wr[k];
#pragma unroll
        for (int j = 0; j < AL; j++) acc[j] += sad[j*DIMN + k] * w;
    }
#pragma unroll
    for (int j = 0; j < AL; j++) {
        float v = acc[j];
#pragma unroll
        for (int o = 16; o; o >>= 1) v += __shfl_xor_sync(0xffffffffu, v, o);
        if (lane == 0) O[(size_t)j*DIMN + n] = v;
    }
}

// ---------------- kernel 2: fused QKV projection + RoPE ----------------
__global__ __launch_bounds__(256) void qkv_kernel(const float* __restrict__ x,
                                                  const float* __restrict__ wq,
                                                  const float* __restrict__ wk,
                                                  const float* __restrict__ wv,
                                                  const float* __restrict__ fc,
                                                  const float* __restrict__ fs) {
    const int z = blockIdx.z;
    const float* B = (z == 0) ? wq : (z == 1) ? wk : wv;
    float* C       = (z == 0) ? g_q : (z == 1) ? g_k : g_v;
    const int bm = blockIdx.y * 128, bn = blockIdx.x * 128;

    float acc[4][4][4];
#pragma unroll
    for (int i = 0; i < 4; i++)
#pragma unroll
        for (int j = 0; j < 4; j++)
#pragma unroll
            for (int e = 0; e < 4; e++) acc[i][j][e] = 0.f;

    gemm128(x + (size_t)bm*DIMN, DIMN, B + (size_t)bn*DIMN, DIMN, DIMN/32, acc);

    const int lane = threadIdx.x & 31, wid = threadIdx.x >> 5;
    const int wm = wid >> 2, wn = wid & 3, ar = lane >> 2, ac = lane & 3;
#pragma unroll
    for (int mt = 0; mt < 4; mt++)
#pragma unroll
        for (int nt = 0; nt < 4; nt++) {
            int r0 = bm + wm*64 + mt*16 + ar, r1 = r0 + 8;
            int col = bn + wn*32 + nt*8 + 2*ac;
            float a0 = acc[mt][nt][0], a1 = acc[mt][nt][1];
            float a2 = acc[mt][nt][2], a3 = acc[mt][nt][3];
            if (z < 2) {  // rope for q,k
                int p  = (col & (HD-1)) >> 1;
                int t0 = r0 & (SEQN-1), t1 = r1 & (SEQN-1);
                float c0 = fc[t0*(HD/2) + p], s0 = fs[t0*(HD/2) + p];
                float c1 = fc[t1*(HD/2) + p], s1 = fs[t1*(HD/2) + p];
                float b0 = a0*c0 - a1*s0, b1 = a0*s0 + a1*c0;
                float b2 = a2*c1 - a3*s1, b3 = a2*s1 + a3*c1;
                if (z == 0) { b0 *= SCALE_Q; b1 *= SCALE_Q; b2 *= SCALE_Q; b3 *= SCALE_Q; }
                a0 = b0; a1 = b1; a2 = b2; a3 = b3;
            }
            *(float2*)(C + (size_t)r0*DIMN + col) = make_float2(a0, a1);
            *(float2*)(C + (size_t)r1*DIMN + col) = make_float2(a2, a3);
        }
}

// ---------------- kernel 3: fused flash attention (S + softmax + PV + adapter) ----
// grid: (8 row-tiles, 32 bh). 256 thr, warp w owns rows [bm + 16w, bm + 16w + 16).
__global__ __launch_bounds__(256, 1) void flash_kernel(const float* __restrict__ g1,
                                                       const float* __restrict__ g2v,
                                                       const int* __restrict__ vsp) {
    extern __shared__ float sm[];
    float* Ks = sm;                      // 2 * 64*KP
    float* Vs = sm + 2*KSTG;             // 2 * 64*KP (raw V staging)
    float* Vt = sm + 4*KSTG;             // 128*VP (V transposed [d][j])
    float* Ps = Vt + 128*VP;             // 128*PP

    const int t = threadIdx.x, lane = t & 31, wid = t >> 5;
    const int ar = lane >> 2, ac = lane & 3;
    const int rtile = blockIdx.x, z = blockIdx.y, b = z >> 4, h = z & (NH-1);
    const int bm = rtile * BM;
    const int vs = vsp[0];
    const float g2 = g2v[h];

    const float* Qg = g_q + ((size_t)(b*SEQN + bm + wid*16))*DIMN + h*HD;
    const float* Kg = g_k + ((size_t)(b*SEQN))*DIMN + h*HD;
    const float* Vg = g_v + ((size_t)(b*SEQN))*DIMN + h*HD;

    // Q fragments (rope+scale already applied): rows [wid*16+ar, +8], all 128 k
    uint32_t qa[16][4];
#pragma unroll
    for (int kt = 0; kt < 16; kt++) {
        const float* p = Qg + (size_t)ar*DIMN + kt*8 + ac;
        qa[kt][0] = ld_tf32(p);
        qa[kt][1] = ld_tf32(p + 8*DIMN);
        qa[kt][2] = ld_tf32(p + 4);
        qa[kt][3] = ld_tf32(p + 8*DIMN + 4);
    }

    float oa[16][4];
#pragma unroll
    for (int n = 0; n < 16; n++)
#pragma unroll
        for (int e = 0; e < 4; e++) oa[n][e] = 0.f;
    float m0 = -1e30f, m1 = -1e30f, l0 = 0.f, l1 = 0.f;

    const int NT = 2*(rtile + 1);
    const int i0 = bm + wid*16 + ar;     // rows i0, i0+8

    auto issueKV = [&](int jt, int buf) {
        const float* Kgt = Kg + (size_t)(jt*BN)*DIMN;
        const float* Vgt = Vg + (size_t)(jt*BN)*DIMN;
        float* Kb = Ks + buf*KSTG;
        float* Vb = Vs + buf*KSTG;
#pragma unroll
        for (int p = 0; p < 8; p++) {
            int r = p*8 + wid, c = lane*4;
            cpa16(Kb + r*KP + c, Kgt + (size_t)r*DIMN + c);
            cpa16(Vb + r*KP + c, Vgt + (size_t)r*DIMN + c);
        }
        cpa_commit();
    };

    issueKV(0, 0);
    for (int jt = 0; jt < NT; jt++) {
        const int buf = jt & 1;
        if (jt + 1 < NT) { issueKV(jt + 1, buf ^ 1); CP_WAIT1(); }
        else             { CP_WAIT0(); }
        __syncthreads();

        // transpose V stage -> Vt[d][j]
        {
            const float* Vb = Vs + buf*KSTG;
#pragma unroll
            for (int half = 0; half < 2; half++) {
                int j = lane + half*32;
                const float* src = Vb + j*KP + wid*16;
                float4 v0 = *(const float4*)(src);
                float4 v1 = *(const float4*)(src + 4);
                float4 v2 = *(const float4*)(src + 8);
                float4 v3 = *(const float4*)(src + 12);
                float* dst = Vt + (wid*16)*VP + j;
                dst[0*VP] = v0.x; dst[1*VP] = v0.y; dst[2*VP]  = v0.z; dst[3*VP]  = v0.w;
                dst[4*VP] = v1.x; dst[5*VP] = v1.y; dst[6*VP]  = v1.z; dst[7*VP]  = v1.w;
                dst[8*VP] = v2.x; dst[9*VP] = v2.y; dst[10*VP] = v2.z; dst[11*VP] = v2.w;
                dst[12*VP]= v3.x; dst[13*VP]= v3.y; dst[14*VP] = v3.z; dst[15*VP] = v3.w;
            }
        }

        // S = Q K^T  (16 rows x 64 cols per warp)
        float sc[8][4];
#pragma unroll
        for (int n = 0; n < 8; n++)
#pragma unroll
            for (int e = 0; e < 4; e++) sc[n][e] = 0.f;
        {
            const float* Kb = Ks + buf*KSTG;
#pragma unroll
            for (int kt = 0; kt < 16; kt++) {
                uint32_t bf[8][2];
#pragma unroll
                for (int nt = 0; nt < 8; nt++) {
                    const float* p = Kb + (nt*8 + ar)*KP + kt*8 + ac;
                    bf[nt][0] = ld_tf32(p);
                    bf[nt][1] = ld_tf32(p + 4);
                }
#pragma unroll
                for (int nt = 0; nt < 8; nt++) mma_tf32(sc[nt], qa[kt], bf[nt]);
            }
        }

        const int j0 = jt*BN;
        // gate2 patch (pre-softmax)
        if (j0 < vs + AL && j0 + BN > vs) {
#pragma unroll
            for (int nt = 0; nt < 8; nt++)
#pragma unroll
                for (int e = 0; e < 4; e++) {
                    int j = j0 + nt*8 + 2*ac + (e & 1);
                    int i = i0 + (e >> 1)*8;
                    if (i >= vs + AL && j >= vs && j < vs + AL) sc[nt][e] += g2;
                }
        }
        // causal mask on the 2 diagonal tiles
        if (jt >= 2*rtile) {
#pragma unroll
            for (int nt = 0; nt < 8; nt++)
#pragma unroll
                for (int e = 0; e < 4; e++) {
                    int j = j0 + nt*8 + 2*ac + (e & 1);
                    int i = i0 + (e >> 1)*8;
                    if (j > i) sc[nt][e] = -1e30f;
                }
        }

        // online softmax (rows i0 / i0+8, each spread over the 4-lane quad)
        float tm0 = -1e30f, tm1 = -1e30f;
#pragma unroll
        for (int nt = 0; nt < 8; nt++) {
            tm0 = fmaxf(tm0, fmaxf(sc[nt][0], sc[nt][1]));
            tm1 = fmaxf(tm1, fmaxf(sc[nt][2], sc[nt][3]));
        }
        tm0 = qredmax(tm0); tm1 = qredmax(tm1);
        float nm0 = fmaxf(m0, tm0), nm1 = fmaxf(m1, tm1);
        float f0 = __expf(m0 - nm0), f1 = __expf(m1 - nm1);
        float s0 = 0.f, s1 = 0.f;
#pragma unroll
        for (int nt = 0; nt < 8; nt++) {
            sc[nt][0] = __expf(sc[nt][0] - nm0); s0 += sc[nt][0];
            sc[nt][1] = __expf(sc[nt][1] - nm0); s0 += sc[nt][1];
            sc[nt][2] = __expf(sc[nt][2] - nm1); s1 += sc[nt][2];
            sc[nt][3] = __expf(sc[nt][3] - nm1); s1 += sc[nt][3];
        }
        s0 = qredsum(s0); s1 = qredsum(s1);
        l0 = l0*f0 + s0; l1 = l1*f1 + s1;
        m0 = nm0; m1 = nm1;
#pragma unroll
        for (int nt = 0; nt < 16; nt++) {
            oa[nt][0] *= f0; oa[nt][1] *= f0;
            oa[nt][2] *= f1; oa[nt][3] *= f1;
        }

        // P -> smem (per-warp private region)
        {
            float* Pw = Ps + (wid*16 + ar)*PP;
#pragma unroll
            for (int nt = 0; nt < 8; nt++) {
                *(float2*)(Pw + nt*8 + 2*ac)          = make_float2(sc[nt][0], sc[nt][1]);
                *(float2*)(Pw + 8*PP + nt*8 + 2*ac)   = make_float2(sc[nt][2], sc[nt][3]);
            }
        }
        __syncthreads();   // Vt written by all warps must be visible; also orders Ps per-warp

        // O += P V
#pragma unroll
        for (int kt = 0; kt < 8; kt++) {
            uint32_t af[4];
            const float* pp = Ps + (wid*16 + ar)*PP + kt*8 + ac;
            af[0] = ld_tf32(pp);
            af[1] = ld_tf32(pp + 8*PP);
            af[2] = ld_tf32(pp + 4);
            af[3] = ld_tf32(pp + 8*PP + 4);
#pragma unroll
            for (int nt = 0; nt < 16; nt++) {
                const float* vp = Vt + (nt*8 + ar)*VP + kt*8 + ac;
                uint32_t bb[2] = { ld_tf32(vp), ld_tf32(vp + 4) };
                mma_tf32(oa[nt], af, bb);
            }
        }
    }

    // normalize
    float inv0 = 1.0f / l0, inv1 = 1.0f / l1;
#pragma unroll
    for (int nt = 0; nt < 16; nt++) {
        oa[nt][0] *= inv0; oa[nt][1] *= inv0;
        oa[nt][2] *= inv1; oa[nt][3] *= inv1;
    }

    // ---- adapter branch ----
    __syncthreads();   // all PV reads done before restaging Ks/Vt
#pragma unroll
    for (int p = 0; p < 8; p++) {
        int idx = p*256 + t;           // 0..2047
        int r = idx >> 7, c = idx & 127;
        Ks[r*KP + c] = (r < AL) ? g_ak[(size_t)r*DIMN + h*HD + c] : 0.f;
        int d = idx >> 4, j = idx & 15;
        Vt[d*VP + j] = (j < AL) ? g_av[(size_t)j*DIMN + h*HD + d] : 0.f;
    }
    __syncthreads();

    float sa[2][4];
#pragma unroll
    for (int n = 0; n < 2; n++)
#pragma unroll
        for (int e = 0; e < 4; e++) sa[n][e] = 0.f;
#pragma unroll
    for (int kt = 0; kt < 16; kt++) {
#pragma unroll
        for (int nt = 0; nt < 2; nt++) {
            const float* p = Ks + (nt*8 + ar)*KP + kt*8 + ac;
            uint32_t bb[2] = { ld_tf32(p), ld_tf32(p + 4) };
            mma_tf32(sa[nt], qa[kt], bb);
        }
    }
#pragma unroll
    for (int nt = 0; nt < 2; nt++)
#pragma unroll
        for (int e = 0; e < 4; e++) {
            int j = nt*8 + 2*ac + (e & 1);
            if (j >= AL) sa[nt][e] = -1e30f;
        }
    float am0 = -1e30f, am1 = -1e30f;
#pragma unroll
    for (int nt = 0; nt < 2; nt++) {
        am0 = fmaxf(am0, fmaxf(sa[nt][0], sa[nt][1]));
        am1 = fmaxf(am1, fmaxf(sa[nt][2], sa[nt][3]));
    }
    am0 = qredmax(am0); am1 = qredmax(am1);
    float as0 = 0.f, as1 = 0.f;
#pragma unroll
    for (int nt = 0; nt < 2; nt++) {
        sa[nt][0] = __expf(sa[nt][0] - am0); as0 += sa[nt][0];
        sa[nt][1] = __expf(sa[nt][1] - am0); as0 += sa[nt][1];
        sa[nt][2] = __expf(sa[nt][2] - am1); as1 += sa[nt][2];
        sa[nt][3] = __expf(sa[nt][3] - am1); as1 += sa[nt][3];
    }
    as0 = qredsum(as0); as1 = qredsum(as1);
    const float tg = tanhf(g1[h]);
    float w0 = tg / as0, w1 = tg / as1;
    {
        float* Pw = Ps + (wid*16 + ar)*PP;
#pragma unroll
        for (int nt = 0; nt < 2; nt++) {
            *(float2*)(Pw + nt*8 + 2*ac)        = make_float2(sa[nt][0]*w0, sa[nt][1]*w0);
            *(float2*)(Pw + 8*PP + nt*8 + 2*ac) = make_float2(sa[nt][2]*w1, sa[nt][3]*w1);
        }
    }
    __syncwarp();
#pragma unroll
    for (int kt = 0; kt < 2; kt++) {
        uint32_t af[4];
        const float* pp = Ps + (wid*16 + ar)*PP + kt*8 + ac;
        af[0] = ld_tf32(pp);
        af[1] = ld_tf32(pp + 8*PP);
        af[2] = ld_tf32(pp + 4);
        af[3] = ld_tf32(pp + 8*PP + 4);
#pragma unroll
        for (int nt = 0; nt < 16; nt++) {
            const float* vp = Vt + (nt*8 + ar)*VP + kt*8 + ac;
            uint32_t bb[2] = { ld_tf32(vp), ld_tf32(vp + 4) };
            mma_tf32(oa[nt], af, bb);
        }
    }

    // write O
    float* Ob = g_ao + ((size_t)(b*SEQN + i0))*DIMN + h*HD;
#pragma unroll
    for (int nt = 0; nt < 16; nt++) {
        int d = nt*8 + 2*ac;
        *(float2*)(Ob + d)            = make_float2(oa[nt][0], oa[nt][1]);
        *(float2*)(Ob + 8*DIMN + d)   = make_float2(oa[nt][2], oa[nt][3]);
    }
}

// ---------------- kernel 4: final projection out = ao @ wo^T ----------------
__global__ __launch_bounds__(256) void wo_kernel(const float* __restrict__ wo,
                                                 float* __restrict__ out) {
    const int bm = blockIdx.y * 128, bn = blockIdx.x * 128;
    float acc[4][4][4];
#pragma unroll
    for (int i = 0; i < 4; i++)
#pragma unroll
        for (int j = 0; j < 4; j++)
#pragma unroll
            for (int e = 0; e < 4; e++) acc[i][j][e] = 0.f;

    gemm128(g_ao + (size_t)bm*DIMN, DIMN, wo + (size_t)bn*DIMN, DIMN, DIMN/32, acc);

    const int lane = threadIdx.x & 31, wid = threadIdx.x >> 5;
    const int wm = wid >> 2, wn = wid & 3, ar = lane >> 2, ac = lane & 3;
#pragma unroll
    for (int mt = 0; mt < 4; mt++)
#pragma unroll
        for (int nt = 0; nt < 4; nt++) {
            int r0 = bm + wm*64 + mt*16 + ar, r1 = r0 + 8;
            int col = bn + wn*32 + nt*8 + 2*ac;
            *(float2*)(out + (size_t)r0*DIMN + col) = make_float2(acc[mt][nt][0], acc[mt][nt][1]);
            *(float2*)(out + (size_t)r1*DIMN + col) = make_float2(acc[mt][nt][2], acc[mt][nt][3]);
        }
}

// ---------------- launch ----------------
extern "C" void kernel_launch(void* const* d_in, const int* in_sizes, int n_in,
                              void* d_out, int out_size) {
    const float* x       = (const float*)d_in[0];
    const float* adapter = (const float*)d_in[1];
    // d_in[2] = mask (triu -1e9, handled analytically)
    const float* fc      = (const float*)d_in[3];
    const float* fs      = (const float*)d_in[4];
    const float* wq      = (const float*)d_in[5];
    const float* wk      = (const float*)d_in[6];
    const float* wv      = (const float*)d_in[7];
    const float* wo      = (const float*)d_in[8];
    const float* g1      = (const float*)d_in[9];
    const float* g2      = (const float*)d_in[10];
    const int*   vs      = (const int*)  d_in[11];
    float* out = (float*)d_out;

    const int smGemm  = 2 * 2 * STG128 * (int)sizeof(float);               // 73728
    const int smAkv   = AL * DIMN * (int)sizeof(float);                    // 81920
    const int smFlash = (4*KSTG + 128*VP + 128*PP) * (int)sizeof(float);   // 204800
    cudaFuncSetAttribute(qkv_kernel,   cudaFuncAttributeMaxDynamicSharedMemorySize, smGemm);
    cudaFuncSetAttribute(wo_kernel,    cudaFuncAttributeMaxDynamicSharedMemorySize, smGemm);
    cudaFuncSetAttribute(akv_kernel,   cudaFuncAttributeMaxDynamicSharedMemorySize, smAkv);
    cudaFuncSetAttribute(flash_kernel, cudaFuncAttributeMaxDynamicSharedMemorySize, smFlash);

    akv_kernel<<<512, 256, smAkv>>>(adapter, wk, wv);
    qkv_kernel<<<dim3(16, 16, 3), 256, smGemm>>>(x, wq, wk, wv, fc, fs);
    flash_kernel<<<dim3(8, 32), 256, smFlash>>>(g1, g2, vs);
    wo_kernel<<<dim3(16, 16), 256, smGemm>>>(wo, out);
}

// round 7
// speedup vs baseline: 1.5714x; 1.0947x over previous
#include <cuda_runtime.h>
#include <math.h>
#include <stdint.h>
#include <stddef.h>

// ---------------- problem constants ----------------
#define SEQN   1024
#define DIMN   2048
#define NTOK   2048          // BSZ*SEQ
#define NH     16
#define HD     128
#define AL     10
#define SCALE_Q 0.08838834764831845f   // 1/sqrt(128)

#define GP     36            // gemm smem pitch (floats)
#define STG128 (128*GP)

// flash tiling
#define BM 128
#define BN 64
#define KP 132               // K/V-staging smem pitch
#define VP 68                // V^T pitch
#define PP 68                // P pitch
#define KSTG (64*KP)         // floats per K/V stage

// ---------------- device scratch (no allocation allowed) ----------------
__device__ float g_q [NTOK*DIMN];
__device__ float g_k [NTOK*DIMN];
__device__ float g_v [NTOK*DIMN];
__device__ float g_ao[NTOK*DIMN];
__device__ float g_ak[AL*DIMN];
__device__ float g_av[AL*DIMN];
// tf32-rounded copies of inputs (so mma hot loops need no CVT)
__device__ float g_xc[NTOK*DIMN];
__device__ float g_wq[DIMN*DIMN];
__device__ float g_wk[DIMN*DIMN];
__device__ float g_wv[DIMN*DIMN];
__device__ float g_wo[DIMN*DIMN];

// ---------------- helpers ----------------
__device__ __forceinline__ float rnaf(float x) {   // round-to-nearest tf32, as float
    uint32_t u;
    asm("cvt.rna.tf32.f32 %0, %1;" : "=r"(u) : "f"(x));
    return __uint_as_float(u);
}
__device__ __forceinline__ uint32_t ldf(const float* p) { return __float_as_uint(*p); }

__device__ __forceinline__ void mma_tf32(float c[4], const uint32_t a[4], const uint32_t b[2]) {
    asm volatile(
        "mma.sync.aligned.m16n8k8.row.col.f32.tf32.tf32.f32 "
        "{%0,%1,%2,%3}, {%4,%5,%6,%7}, {%8,%9}, {%0,%1,%2,%3};"
        : "+f"(c[0]), "+f"(c[1]), "+f"(c[2]), "+f"(c[3])
        : "r"(a[0]), "r"(a[1]), "r"(a[2]), "r"(a[3]), "r"(b[0]), "r"(b[1]));
}

__device__ __forceinline__ void cpa16(float* s, const float* g) {
    unsigned sa = (unsigned)__cvta_generic_to_shared(s);
    asm volatile("cp.async.cg.shared.global [%0], [%1], 16;\n" :: "r"(sa), "l"(g));
}
__device__ __forceinline__ void cpa_commit() { asm volatile("cp.async.commit_group;\n" ::); }
#define CP_WAIT1() asm volatile("cp.async.wait_group 1;\n" ::)
#define CP_WAIT0() asm volatile("cp.async.wait_group 0;\n" ::)

__device__ __forceinline__ float qredmax(float v) {
    v = fmaxf(v, __shfl_xor_sync(0xffffffffu, v, 1));
    v = fmaxf(v, __shfl_xor_sync(0xffffffffu, v, 2));
    return v;
}
__device__ __forceinline__ float qredsum(float v) {
    v += __shfl_xor_sync(0xffffffffu, v, 1);
    v += __shfl_xor_sync(0xffffffffu, v, 2);
    return v;
}

// ---------------- kernel 0: tf32-round x + 4 weights into scratch ----------------
__global__ __launch_bounds__(256) void cvt_kernel(const float* __restrict__ x,
                                                  const float* __restrict__ wq,
                                                  const float* __restrict__ wk,
                                                  const float* __restrict__ wv,
                                                  const float* __restrict__ wo) {
    const float* s; float* d;
    switch (blockIdx.y) {
        case 0: s = x;  d = g_xc; break;
        case 1: s = wq; d = g_wq; break;
        case 2: s = wk; d = g_wk; break;
        case 3: s = wv; d = g_wv; break;
        default: s = wo; d = g_wo; break;
    }
    size_t i = ((size_t)blockIdx.x * 256 + threadIdx.x) * 4;
    float4 v = *(const float4*)(s + i);
    v.x = rnaf(v.x); v.y = rnaf(v.y); v.z = rnaf(v.z); v.w = rnaf(v.w);
    *(float4*)(d + i) = v;
}

// fragment loop over one 32-k stage (operands pre-rounded; plain LDS)
template<int MT>
__device__ __forceinline__ void mma_stage(const float* Ab, const float* Bb,
                                          float (*acc)[4][4], int ar, int ac) {
#pragma unroll
    for (int ks = 0; ks < 4; ks++) {
        const int k0 = ks * 8;
        uint32_t af[MT][4], bf[4][2];
#pragma unroll
        for (int mt = 0; mt < MT; mt++) {
            const float* p = Ab + (mt*16 + ar)*GP + k0 + ac;
            af[mt][0] = ldf(p);
            af[mt][1] = ldf(p + 8*GP);
            af[mt][2] = ldf(p + 4);
            af[mt][3] = ldf(p + 8*GP + 4);
        }
#pragma unroll
        for (int nt = 0; nt < 4; nt++) {
            const float* p = Bb + (nt*8 + ar)*GP + k0 + ac;
            bf[nt][0] = ldf(p);
            bf[nt][1] = ldf(p + 4);
        }
#pragma unroll
        for (int mt = 0; mt < MT; mt++)
#pragma unroll
            for (int nt = 0; nt < 4; nt++) mma_tf32(acc[mt][nt], af[mt], bf[nt]);
    }
}

// 128x128 C block: C[m][n] = sum_k A[m][k]*B[n][k]. A,B pre-offset to block origin.
__device__ __forceinline__ void gemm128(const float* __restrict__ A, int lda,
                                        const float* __restrict__ B, int ldb,
                                        int nk, float (*acc)[4][4]) {
    extern __shared__ float smdyn[];
    float* As = smdyn;
    float* Bs = smdyn + 2*STG128;
    const int t = threadIdx.x, lane = t & 31, wid = t >> 5;
    const int wm = wid >> 2, wn = wid & 3, ar = lane >> 2, ac = lane & 3;
    const int lr = t >> 3, lc = (t & 7) * 4;

    auto issue = [&](int kt, int buf) {
        float* Asb = As + buf*STG128;
        float* Bsb = Bs + buf*STG128;
        const float* Ag = A + kt*32;
        const float* Bg = B + kt*32;
#pragma unroll
        for (int i = 0; i < 4; i++) {
            int r = lr + i*32;
            cpa16(Asb + r*GP + lc, Ag + (size_t)r*lda + lc);
            cpa16(Bsb + r*GP + lc, Bg + (size_t)r*ldb + lc);
        }
        cpa_commit();
    };

    issue(0, 0);
    for (int kt = 0; kt < nk; kt++) {
        if (kt + 1 < nk) { issue(kt + 1, (kt + 1) & 1); CP_WAIT1(); }
        else             { CP_WAIT0(); }
        __syncthreads();
        mma_stage<4>(As + (kt&1)*STG128 + (wm*64)*GP,
                     Bs + (kt&1)*STG128 + (wn*32)*GP, acc, ar, ac);
        __syncthreads();
    }
}

// ---------------- kernel 1: adapter projections a_k, a_v ----------------
__global__ __launch_bounds__(256) void akv_kernel(const float* __restrict__ adapter,
                                                  const float* __restrict__ wk,
                                                  const float* __restrict__ wv) {
    extern __shared__ float sad[];   // 10*2048 floats = 80KB
    const int t = threadIdx.x, lane = t & 31, wid = t >> 5;
    for (int i = t; i < (AL*DIMN)/4; i += 256)
        ((float4*)sad)[i] = ((const float4*)adapter)[i];
    __syncthreads();

    int gw = blockIdx.x * 8 + wid;          // 0..4095
    const float* W = (gw < DIMN) ? wk : wv;
    float* O       = (gw < DIMN) ? g_ak : g_av;
    int n = gw & (DIMN - 1);
    const float* Wr = W + (size_t)n * DIMN;

    float acc[AL];
#pragma unroll
    for (int j = 0; j < AL; j++) acc[j] = 0.f;

    for (int it = 0; it < DIMN/32; it++) {
        int k = it*32 + lane;
        float w = Wr[k];
#pragma unroll
        for (int j = 0; j < AL; j++) acc[j] += sad[j*DIMN + k] * w;
    }
#pragma unroll
    for (int j = 0; j < AL; j++) {
        float v = acc[j];
#pragma unroll
        for (int o = 16; o; o >>= 1) v += __shfl_xor_sync(0xffffffffu, v, o);
        if (lane == 0) O[(size_t)j*DIMN + n] = rnaf(v);
    }
}

// ---------------- kernel 2: fused QKV projection + RoPE (outputs tf32-rounded) ----
__global__ __launch_bounds__(256) void qkv_kernel(const float* __restrict__ fc,
                                                  const float* __restrict__ fs) {
    const int z = blockIdx.z;
    const float* B = (z == 0) ? g_wq : (z == 1) ? g_wk : g_wv;
    float* C       = (z == 0) ? g_q : (z == 1) ? g_k : g_v;
    const int bm = blockIdx.y * 128, bn = blockIdx.x * 128;

    float acc[4][4][4];
#pragma unroll
    for (int i = 0; i < 4; i++)
#pragma unroll
        for (int j = 0; j < 4; j++)
#pragma unroll
            for (int e = 0; e < 4; e++) acc[i][j][e] = 0.f;

    gemm128(g_xc + (size_t)bm*DIMN, DIMN, B + (size_t)bn*DIMN, DIMN, DIMN/32, acc);

    const int lane = threadIdx.x & 31, wid = threadIdx.x >> 5;
    const int wm = wid >> 2, wn = wid & 3, ar = lane >> 2, ac = lane & 3;
#pragma unroll
    for (int mt = 0; mt < 4; mt++)
#pragma unroll
        for (int nt = 0; nt < 4; nt++) {
            int r0 = bm + wm*64 + mt*16 + ar, r1 = r0 + 8;
            int col = bn + wn*32 + nt*8 + 2*ac;
            float a0 = acc[mt][nt][0], a1 = acc[mt][nt][1];
            float a2 = acc[mt][nt][2], a3 = acc[mt][nt][3];
            if (z < 2) {  // rope for q,k
                int p  = (col & (HD-1)) >> 1;
                int t0 = r0 & (SEQN-1), t1 = r1 & (SEQN-1);
                float c0 = fc[t0*(HD/2) + p], s0 = fs[t0*(HD/2) + p];
                float c1 = fc[t1*(HD/2) + p], s1 = fs[t1*(HD/2) + p];
                float b0 = a0*c0 - a1*s0, b1 = a0*s0 + a1*c0;
                float b2 = a2*c1 - a3*s1, b3 = a2*s1 + a3*c1;
                if (z == 0) { b0 *= SCALE_Q; b1 *= SCALE_Q; b2 *= SCALE_Q; b3 *= SCALE_Q; }
                a0 = b0; a1 = b1; a2 = b2; a3 = b3;
            }
            *(float2*)(C + (size_t)r0*DIMN + col) = make_float2(rnaf(a0), rnaf(a1));
            *(float2*)(C + (size_t)r1*DIMN + col) = make_float2(rnaf(a2), rnaf(a3));
        }
}

// ---------------- kernel 3: fused flash attention (S + softmax + PV + adapter) ----
// grid: (8 row-tiles, 32 bh). 256 thr, warp w owns rows [bm + 16w, bm + 16w + 16).
__global__ __launch_bounds__(256, 1) void flash_kernel(const float* __restrict__ g1,
                                                       const float* __restrict__ g2v,
                                                       const int* __restrict__ vsp) {
    extern __shared__ float sm[];
    float* Ks = sm;                      // 2 * 64*KP
    float* Vs = sm + 2*KSTG;             // 2 * 64*KP (raw V staging)
    float* Vt = sm + 4*KSTG;             // 128*VP (V transposed [d][j])
    float* Ps = Vt + 128*VP;             // 128*PP

    const int t = threadIdx.x, lane = t & 31, wid = t >> 5;
    const int ar = lane >> 2, ac = lane & 3;
    const int rtile = blockIdx.x, z = blockIdx.y, b = z >> 4, h = z & (NH-1);
    const int bm = rtile * BM;
    const int vs = vsp[0];
    const float g2 = g2v[h];

    const float* Qg = g_q + ((size_t)(b*SEQN + bm + wid*16))*DIMN + h*HD;
    const float* Kg = g_k + ((size_t)(b*SEQN))*DIMN + h*HD;
    const float* Vg = g_v + ((size_t)(b*SEQN))*DIMN + h*HD;

    // Q fragments (pre-rounded in g_q): rows [wid*16+ar, +8], all 128 k
    uint32_t qa[16][4];
#pragma unroll
    for (int kt = 0; kt < 16; kt++) {
        const float* p = Qg + (size_t)ar*DIMN + kt*8 + ac;
        qa[kt][0] = ldf(p);
        qa[kt][1] = ldf(p + 8*DIMN);
        qa[kt][2] = ldf(p + 4);
        qa[kt][3] = ldf(p + 8*DIMN + 4);
    }

    float oa[16][4];
#pragma unroll
    for (int n = 0; n < 16; n++)
#pragma unroll
        for (int e = 0; e < 4; e++) oa[n][e] = 0.f;
    float m0 = -1e30f, m1 = -1e30f, l0 = 0.f, l1 = 0.f;

    const int NT = 2*(rtile + 1);
    const int i0 = bm + wid*16 + ar;     // rows i0, i0+8

    auto issueKV = [&](int jt, int buf) {
        const float* Kgt = Kg + (size_t)(jt*BN)*DIMN;
        const float* Vgt = Vg + (size_t)(jt*BN)*DIMN;
        float* Kb = Ks + buf*KSTG;
        float* Vb = Vs + buf*KSTG;
#pragma unroll
        for (int p = 0; p < 8; p++) {
            int r = p*8 + wid, c = lane*4;
            cpa16(Kb + r*KP + c, Kgt + (size_t)r*DIMN + c);
            cpa16(Vb + r*KP + c, Vgt + (size_t)r*DIMN + c);
        }
        cpa_commit();
    };

    issueKV(0, 0);
    for (int jt = 0; jt < NT; jt++) {
        const int buf = jt & 1;
        if (jt + 1 < NT) { issueKV(jt + 1, buf ^ 1); CP_WAIT1(); }
        else             { CP_WAIT0(); }
        __syncthreads();

        // transpose V stage -> Vt[d][j] (already tf32-rounded)
        {
            const float* Vb = Vs + buf*KSTG;
#pragma unroll
            for (int half = 0; half < 2; half++) {
                int j = lane + half*32;
                const float* src = Vb + j*KP + wid*16;
                float4 v0 = *(const float4*)(src);
                float4 v1 = *(const float4*)(src + 4);
                float4 v2 = *(const float4*)(src + 8);
                float4 v3 = *(const float4*)(src + 12);
                float* dst = Vt + (wid*16)*VP + j;
                dst[0*VP] = v0.x; dst[1*VP] = v0.y; dst[2*VP]  = v0.z; dst[3*VP]  = v0.w;
                dst[4*VP] = v1.x; dst[5*VP] = v1.y; dst[6*VP]  = v1.z; dst[7*VP]  = v1.w;
                dst[8*VP] = v2.x; dst[9*VP] = v2.y; dst[10*VP] = v2.z; dst[11*VP] = v2.w;
                dst[12*VP]= v3.x; dst[13*VP]= v3.y; dst[14*VP] = v3.z; dst[15*VP] = v3.w;
            }
        }

        // S = Q K^T  (16 rows x 64 cols per warp)
        float sc[8][4];
#pragma unroll
        for (int n = 0; n < 8; n++)
#pragma unroll
            for (int e = 0; e < 4; e++) sc[n][e] = 0.f;
        {
            const float* Kb = Ks + buf*KSTG;
#pragma unroll
            for (int kt = 0; kt < 16; kt++) {
                uint32_t bf[8][2];
#pragma unroll
                for (int nt = 0; nt < 8; nt++) {
                    const float* p = Kb + (nt*8 + ar)*KP + kt*8 + ac;
                    bf[nt][0] = ldf(p);
                    bf[nt][1] = ldf(p + 4);
                }
#pragma unroll
                for (int nt = 0; nt < 8; nt++) mma_tf32(sc[nt], qa[kt], bf[nt]);
            }
        }

        const int j0 = jt*BN;
        // gate2 patch (pre-softmax)
        if (j0 < vs + AL && j0 + BN > vs) {
#pragma unroll
            for (int nt = 0; nt < 8; nt++)
#pragma unroll
                for (int e = 0; e < 4; e++) {
                    int j = j0 + nt*8 + 2*ac + (e & 1);
                    int i = i0 + (e >> 1)*8;
                    if (i >= vs + AL && j >= vs && j < vs + AL) sc[nt][e] += g2;
                }
        }
        // causal mask on the 2 diagonal tiles
        if (jt >= 2*rtile) {
#pragma unroll
            for (int nt = 0; nt < 8; nt++)
#pragma unroll
                for (int e = 0; e < 4; e++) {
                    int j = j0 + nt*8 + 2*ac + (e & 1);
                    int i = i0 + (e >> 1)*8;
                    if (j > i) sc[nt][e] = -1e30f;
                }
        }

        // online softmax (rows i0 / i0+8, each spread over the 4-lane quad)
        float tm0 = -1e30f, tm1 = -1e30f;
#pragma unroll
        for (int nt = 0; nt < 8; nt++) {
            tm0 = fmaxf(tm0, fmaxf(sc[nt][0], sc[nt][1]));
            tm1 = fmaxf(tm1, fmaxf(sc[nt][2], sc[nt][3]));
        }
        tm0 = qredmax(tm0); tm1 = qredmax(tm1);
        float nm0 = fmaxf(m0, tm0), nm1 = fmaxf(m1, tm1);
        float f0 = __expf(m0 - nm0), f1 = __expf(m1 - nm1);
        float s0 = 0.f, s1 = 0.f;
#pragma unroll
        for (int nt = 0; nt < 8; nt++) {
            sc[nt][0] = __expf(sc[nt][0] - nm0); s0 += sc[nt][0];
            sc[nt][1] = __expf(sc[nt][1] - nm0); s0 += sc[nt][1];
            sc[nt][2] = __expf(sc[nt][2] - nm1); s1 += sc[nt][2];
            sc[nt][3] = __expf(sc[nt][3] - nm1); s1 += sc[nt][3];
        }
        s0 = qredsum(s0); s1 = qredsum(s1);
        l0 = l0*f0 + s0; l1 = l1*f1 + s1;
        m0 = nm0; m1 = nm1;
#pragma unroll
        for (int nt = 0; nt < 16; nt++) {
            oa[nt][0] *= f0; oa[nt][1] *= f0;
            oa[nt][2] *= f1; oa[nt][3] *= f1;
        }

        // P -> smem (per-warp private region), rounded at store
        {
            float* Pw = Ps + (wid*16 + ar)*PP;
#pragma unroll
            for (int nt = 0; nt < 8; nt++) {
                *(float2*)(Pw + nt*8 + 2*ac)          = make_float2(rnaf(sc[nt][0]), rnaf(sc[nt][1]));
                *(float2*)(Pw + 8*PP + nt*8 + 2*ac)   = make_float2(rnaf(sc[nt][2]), rnaf(sc[nt][3]));
            }
        }
        __syncthreads();   // Vt written by all warps must be visible; also orders Ps per-warp

        // O += P V
#pragma unroll
        for (int kt = 0; kt < 8; kt++) {
            uint32_t af[4];
            const float* pp = Ps + (wid*16 + ar)*PP + kt*8 + ac;
            af[0] = ldf(pp);
            af[1] = ldf(pp + 8*PP);
            af[2] = ldf(pp + 4);
            af[3] = ldf(pp + 8*PP + 4);
#pragma unroll
            for (int nt = 0; nt < 16; nt++) {
                const float* vp = Vt + (nt*8 + ar)*VP + kt*8 + ac;
                uint32_t bb[2] = { ldf(vp), ldf(vp + 4) };
                mma_tf32(oa[nt], af, bb);
            }
        }
    }

    // normalize
    float inv0 = 1.0f / l0, inv1 = 1.0f / l1;
#pragma unroll
    for (int nt = 0; nt < 16; nt++) {
        oa[nt][0] *= inv0; oa[nt][1] *= inv0;
        oa[nt][2] *= inv1; oa[nt][3] *= inv1;
    }

    // ---- adapter branch ----
    __syncthreads();   // all PV reads done before restaging Ks/Vt
#pragma unroll
    for (int p = 0; p < 8; p++) {
        int idx = p*256 + t;           // 0..2047
        int r = idx >> 7, c = idx & 127;
        Ks[r*KP + c] = (r < AL) ? g_ak[(size_t)r*DIMN + h*HD + c] : 0.f;
        int d = idx >> 4, j = idx & 15;
        Vt[d*VP + j] = (j < AL) ? g_av[(size_t)j*DIMN + h*HD + d] : 0.f;
    }
    __syncthreads();

    float sa[2][4];
#pragma unroll
    for (int n = 0; n < 2; n++)
#pragma unroll
        for (int e = 0; e < 4; e++) sa[n][e] = 0.f;
#pragma unroll
    for (int kt = 0; kt < 16; kt++) {
#pragma unroll
        for (int nt = 0; nt < 2; nt++) {
            const float* p = Ks + (nt*8 + ar)*KP + kt*8 + ac;
            uint32_t bb[2] = { ldf(p), ldf(p + 4) };
            mma_tf32(sa[nt], qa[kt], bb);
        }
    }
#pragma unroll
    for (int nt = 0; nt < 2; nt++)
#pragma unroll
        for (int e = 0; e < 4; e++) {
            int j = nt*8 + 2*ac + (e & 1);
            if (j >= AL) sa[nt][e] = -1e30f;
        }
    float am0 = -1e30f, am1 = -1e30f;
#pragma unroll
    for (int nt = 0; nt < 2; nt++) {
        am0 = fmaxf(am0, fmaxf(sa[nt][0], sa[nt][1]));
        am1 = fmaxf(am1, fmaxf(sa[nt][2], sa[nt][3]));
    }
    am0 = qredmax(am0); am1 = qredmax(am1);
    float as0 = 0.f, as1 = 0.f;
#pragma unroll
    for (int nt = 0; nt < 2; nt++) {
        sa[nt][0] = __expf(sa[nt][0] - am0); as0 += sa[nt][0];
        sa[nt][1] = __expf(sa[nt][1] - am0); as0 += sa[nt][1];
        sa[nt][2] = __expf(sa[nt][2] - am1); as1 += sa[nt][2];
        sa[nt][3] = __expf(sa[nt][3] - am1); as1 += sa[nt][3];
    }
    as0 = qredsum(as0); as1 = qredsum(as1);
    const float tg = tanhf(g1[h]);
    float w0 = tg / as0, w1 = tg / as1;
    {
        float* Pw = Ps + (wid*16 + ar)*PP;
#pragma unroll
        for (int nt = 0; nt < 2; nt++) {
            *(float2*)(Pw + nt*8 + 2*ac)        = make_float2(rnaf(sa[nt][0]*w0), rnaf(sa[nt][1]*w0));
            *(float2*)(Pw + 8*PP + nt*8 + 2*ac) = make_float2(rnaf(sa[nt][2]*w1), rnaf(sa[nt][3]*w1));
        }
    }
    __syncwarp();
#pragma unroll
    for (int kt = 0; kt < 2; kt++) {
        uint32_t af[4];
        const float* pp = Ps + (wid*16 + ar)*PP + kt*8 + ac;
        af[0] = ldf(pp);
        af[1] = ldf(pp + 8*PP);
        af[2] = ldf(pp + 4);
        af[3] = ldf(pp + 8*PP + 4);
#pragma unroll
        for (int nt = 0; nt < 16; nt++) {
            const float* vp = Vt + (nt*8 + ar)*VP + kt*8 + ac;
            uint32_t bb[2] = { ldf(vp), ldf(vp + 4) };
            mma_tf32(oa[nt], af, bb);
        }
    }

    // write O (rounded, so wo_kernel needs no CVT)
    float* Ob = g_ao + ((size_t)(b*SEQN + i0))*DIMN + h*HD;
#pragma unroll
    for (int nt = 0; nt < 16; nt++) {
        int d = nt*8 + 2*ac;
        *(float2*)(Ob + d)            = make_float2(rnaf(oa[nt][0]), rnaf(oa[nt][1]));
        *(float2*)(Ob + 8*DIMN + d)   = make_float2(rnaf(oa[nt][2]), rnaf(oa[nt][3]));
    }
}

// ---------------- kernel 4: final projection out = ao @ wo^T ----------------
__global__ __launch_bounds__(256) void wo_kernel(float* __restrict__ out) {
    const int bm = blockIdx.y * 128, bn = blockIdx.x * 128;
    float acc[4][4][4];
#pragma unroll
    for (int i = 0; i < 4; i++)
#pragma unroll
        for (int j = 0; j < 4; j++)
#pragma unroll
            for (int e = 0; e < 4; e++) acc[i][j][e] = 0.f;

    gemm128(g_ao + (size_t)bm*DIMN, DIMN, g_wo + (size_t)bn*DIMN, DIMN, DIMN/32, acc);

    const int lane = threadIdx.x & 31, wid = threadIdx.x >> 5;
    const int wm = wid >> 2, wn = wid & 3, ar = lane >> 2, ac = lane & 3;
#pragma unroll
    for (int mt = 0; mt < 4; mt++)
#pragma unroll
        for (int nt = 0; nt < 4; nt++) {
            int r0 = bm + wm*64 + mt*16 + ar, r1 = r0 + 8;
            int col = bn + wn*32 + nt*8 + 2*ac;
            *(float2*)(out + (size_t)r0*DIMN + col) = make_float2(acc[mt][nt][0], acc[mt][nt][1]);
            *(float2*)(out + (size_t)r1*DIMN + col) = make_float2(acc[mt][nt][2], acc[mt][nt][3]);
        }
}

// ---------------- launch ----------------
extern "C" void kernel_launch(void* const* d_in, const int* in_sizes, int n_in,
                              void* d_out, int out_size) {
    const float* x       = (const float*)d_in[0];
    const float* adapter = (const float*)d_in[1];
    // d_in[2] = mask (triu -1e9, handled analytically)
    const float* fc      = (const float*)d_in[3];
    const float* fs      = (const float*)d_in[4];
    const float* wq      = (const float*)d_in[5];
    const float* wk      = (const float*)d_in[6];
    const float* wv      = (const float*)d_in[7];
    const float* wo      = (const float*)d_in[8];
    const float* g1      = (const float*)d_in[9];
    const float* g2      = (const float*)d_in[10];
    const int*   vs      = (const int*)  d_in[11];
    float* out = (float*)d_out;

    const int smGemm  = 2 * 2 * STG128 * (int)sizeof(float);               // 73728
    const int smAkv   = AL * DIMN * (int)sizeof(float);                    // 81920
    const int smFlash = (4*KSTG + 128*VP + 128*PP) * (int)sizeof(float);   // 204800
    cudaFuncSetAttribute(qkv_kernel,   cudaFuncAttributeMaxDynamicSharedMemorySize, smGemm);
    cudaFuncSetAttribute(wo_kernel,    cudaFuncAttributeMaxDynamicSharedMemorySize, smGemm);
    cudaFuncSetAttribute(akv_kernel,   cudaFuncAttributeMaxDynamicSharedMemorySize, smAkv);
    cudaFuncSetAttribute(flash_kernel, cudaFuncAttributeMaxDynamicSharedMemorySize, smFlash);

    cvt_kernel<<<dim3(4096, 5), 256>>>(x, wq, wk, wv, wo);
    akv_kernel<<<512, 256, smAkv>>>(adapter, wk, wv);
    qkv_kernel<<<dim3(16, 16, 3), 256, smGemm>>>(fc, fs);
    flash_kernel<<<dim3(8, 32), 256, smFlash>>>(g1, g2, vs);
    wo_kernel<<<dim3(16, 16), 256, smGemm>>>(out);
}